// round 4
// baseline (speedup 1.0000x reference)
#include <cuda_runtime.h>
#include <math.h>

#define Bv 4
#define Cv 32
#define Sv 64
#define Hv 256
#define ROWS (Cv * Sv)          // 2048 rows per batch
#define NEG_BIG (-1e10f)

#define KT 32                   // K-chunk
#define PW 132                  // padded smem row stride (floats), 16B-aligned, low-conflict

// Scratch (static device arrays; no runtime allocation allowed)
__device__ float g_proj[Bv * ROWS * Hv];       // 8 MB
__device__ float g_w[Bv * Cv * Cv * Sv];       // 2 MB

// ---------------------------------------------------------------------------
// Shared 128x128x256 NT-GEMM mainloop: C[r,c] = sum_k A[r,k]*B[c,k]
// A, B row-major with leading dim 256. Tiles stored transposed in smem
// (sA[k][r]) so fragment loads are conflict-free float4 reads.
// ---------------------------------------------------------------------------
__device__ __forceinline__ void gemm_mainloop(
    const float* __restrict__ Ab,   // A + rowBase*256
    const float* __restrict__ Bb,   // B + colBase*256
    float* sA, float* sB, float acc[8][8], int tid)
{
    const int tx = tid & 15;
    const int ty = tid >> 4;

    for (int k0 = 0; k0 < Hv; k0 += KT) {
        // Load 128x32 of A and B, transposed into smem
        #pragma unroll
        for (int p = 0; p < 4; p++) {
            int idx = tid + p * 256;         // 0..1023
            int r   = idx >> 3;              // 0..127
            int c4  = (idx & 7) << 2;        // 0,4,...,28
            float4 va = *(const float4*)(Ab + r * Hv + k0 + c4);
            float4 vb = *(const float4*)(Bb + r * Hv + k0 + c4);
            sA[(c4 + 0) * PW + r] = va.x;
            sA[(c4 + 1) * PW + r] = va.y;
            sA[(c4 + 2) * PW + r] = va.z;
            sA[(c4 + 3) * PW + r] = va.w;
            sB[(c4 + 0) * PW + r] = vb.x;
            sB[(c4 + 1) * PW + r] = vb.y;
            sB[(c4 + 2) * PW + r] = vb.z;
            sB[(c4 + 3) * PW + r] = vb.w;
        }
        __syncthreads();

        #pragma unroll 1
        for (int kk = 0; kk < KT; kk += 8) {
            #pragma unroll
            for (int u = 0; u < 8; u++) {
                int k = kk + u;
                const float4 a0 = *(const float4*)(sA + k * PW + ty * 8);
                const float4 a1 = *(const float4*)(sA + k * PW + ty * 8 + 4);
                const float4 b0 = *(const float4*)(sB + k * PW + tx * 8);
                const float4 b1 = *(const float4*)(sB + k * PW + tx * 8 + 4);
                float av[8] = {a0.x, a0.y, a0.z, a0.w, a1.x, a1.y, a1.z, a1.w};
                float bv[8] = {b0.x, b0.y, b0.z, b0.w, b1.x, b1.y, b1.z, b1.w};
                #pragma unroll
                for (int i = 0; i < 8; i++)
                    #pragma unroll
                    for (int j = 0; j < 8; j++)
                        acc[i][j] = fmaf(av[i], bv[j], acc[i][j]);
            }
        }
        __syncthreads();
    }
}

// ---------------------------------------------------------------------------
// Kernel 1: proj[m,g] = sum_h inputs[m,h] * W[g,h]   (M=8192, N=256, K=256)
// ---------------------------------------------------------------------------
__global__ __launch_bounds__(256, 2)
void proj_kernel(const float* __restrict__ inp, const float* __restrict__ W)
{
    __shared__ float sA[KT * PW];
    __shared__ float sB[KT * PW];

    const int tid = threadIdx.x;
    const int rowBase = blockIdx.y * 128;
    const int colBase = blockIdx.x * 128;

    float acc[8][8];
    #pragma unroll
    for (int i = 0; i < 8; i++)
        #pragma unroll
        for (int j = 0; j < 8; j++) acc[i][j] = 0.f;

    gemm_mainloop(inp + (size_t)rowBase * Hv, W + (size_t)colBase * Hv, sA, sB, acc, tid);

    const int tx = tid & 15;
    const int ty = tid >> 4;
    #pragma unroll
    for (int i = 0; i < 8; i++) {
        float4 v0 = make_float4(acc[i][0], acc[i][1], acc[i][2], acc[i][3]);
        float4 v1 = make_float4(acc[i][4], acc[i][5], acc[i][6], acc[i][7]);
        float* dst = g_proj + (size_t)(rowBase + ty * 8 + i) * Hv + colBase + tx * 8;
        *(float4*)dst = v0;
        *(float4*)(dst + 4) = v1;
    }
}

// ---------------------------------------------------------------------------
// Kernel 2: per-batch scores GEMM (2048x2048x256) + sigmoid epilogue writing
// att[B,C,C,S,S], plus fused in-tile reduction of
//   w[b,i,j,t] = sum_s att_self[b,i,s] * att[b,i,j,s,t]
// Each 128x128 tile covers exactly 2 i-blocks x 2 j-blocks (S=64), so w is
// produced completely and exactly once per tile. Deterministic smem reduction.
// ---------------------------------------------------------------------------
__global__ __launch_bounds__(256, 2)
void att_kernel(const float* __restrict__ inp, const float* __restrict__ mask,
                const float* __restrict__ aself, float* __restrict__ att_out)
{
    __shared__ float sA[KT * PW];
    __shared__ float sB[KT * PW];
    __shared__ float s_wp[16 * 128];
    __shared__ float s_as[128];

    const int tid = threadIdx.x;
    const int b = blockIdx.z;
    const int rowBase = blockIdx.y * 128;
    const int colBase = blockIdx.x * 128;

    if (tid < 128) s_as[tid] = aself[b * ROWS + rowBase + tid];
    // visibility guaranteed by first __syncthreads inside mainloop

    float acc[8][8];
    #pragma unroll
    for (int i = 0; i < 8; i++)
        #pragma unroll
        for (int j = 0; j < 8; j++) acc[i][j] = 0.f;

    const float* Ab = g_proj + (size_t)(b * ROWS + rowBase) * Hv;
    const float* Bb = inp    + (size_t)(b * ROWS + colBase) * Hv;
    gemm_mainloop(Ab, Bb, sA, sB, acc, tid);

    const int tx = tid & 15;
    const int ty = tid >> 4;

    float mcol[8], wpart[8];
    #pragma unroll
    for (int j = 0; j < 8; j++) {
        mcol[j] = (1.0f - mask[b * ROWS + colBase + tx * 8 + j]) * NEG_BIG;
        wpart[j] = 0.f;
    }

    const int i_idx = blockIdx.y * 2 + (ty >> 3);
    const int j_idx = blockIdx.x * 2 + (tx >> 3);
    const int s0 = (ty * 8) & 63;
    const int t0 = (tx * 8) & 63;
    float* attB = att_out + (((size_t)((b * Cv + i_idx) * Cv + j_idx)) << 12) + t0;

    #pragma unroll
    for (int i = 0; i < 8; i++) {
        float asv = s_as[ty * 8 + i];
        #pragma unroll
        for (int j = 0; j < 8; j++) {
            float x = acc[i][j] + mcol[j];
            float a = 1.0f / (1.0f + expf(-x));   // sigmoid; saturates correctly
            acc[i][j] = a;
            wpart[j] += a * asv;
        }
        float4 v0 = make_float4(acc[i][0], acc[i][1], acc[i][2], acc[i][3]);
        float4 v1 = make_float4(acc[i][4], acc[i][5], acc[i][6], acc[i][7]);
        float* dst = attB + (size_t)(s0 + i) * 64;
        *(float4*)dst = v0;
        *(float4*)(dst + 4) = v1;
    }

    // deterministic per-column reduction of wpart across the 16 thread-rows
    #pragma unroll
    for (int j = 0; j < 8; j++) s_wp[ty * 128 + tx * 8 + j] = wpart[j];
    __syncthreads();

    {
        int rh = tid >> 7;        // which i-half of the tile (rows 0-63 / 64-127)
        int lc = tid & 127;       // local column 0..127
        float s = 0.f;
        #pragma unroll
        for (int yy = 0; yy < 8; yy++) s += s_wp[(rh * 8 + yy) * 128 + lc];
        int ii = blockIdx.y * 2 + rh;
        int jj = blockIdx.x * 2 + (lc >> 6);
        int tt = lc & 63;
        g_w[((b * Cv + ii) * Cv + jj) * Sv + tt] = s;
    }
}

// ---------------------------------------------------------------------------
// Kernel 3: fused[b,i,j,h] = sum_t w[b,i,j,t] * inputs[b,j,t,h]
// One CTA per (b,j): inputs tile cached in registers, looped over i.
// ---------------------------------------------------------------------------
__global__ __launch_bounds__(256)
void fused_kernel(const float* __restrict__ inp, float* __restrict__ fused)
{
    const int j = blockIdx.x;
    const int b = blockIdx.y;
    const int h = threadIdx.x;

    const float* X = inp + (size_t)((b * Cv + j) * Sv) * Hv;
    float xc[64];
    #pragma unroll
    for (int t = 0; t < 64; t++) xc[t] = X[(size_t)t * Hv + h];

    __shared__ float sw[64];
    for (int i = 0; i < Cv; i++) {
        if (h < 64) sw[h] = g_w[((b * Cv + i) * Cv + j) * Sv + h];
        __syncthreads();
        float acc = 0.f;
        #pragma unroll
        for (int t = 0; t < 64; t++) acc = fmaf(sw[t], xc[t], acc);
        fused[(size_t)((b * Cv + i) * Cv + j) * Hv + h] = acc;
        __syncthreads();
    }
}

// ---------------------------------------------------------------------------
extern "C" void kernel_launch(void* const* d_in, const int* in_sizes, int n_in,
                              void* d_out, int out_size)
{
    const float* inputs = (const float*)d_in[0];   // [B,C,S,H]
    const float* mask   = (const float*)d_in[1];   // [B,C,S]
    const float* aself  = (const float*)d_in[2];   // [B,C,S]
    const float* W      = (const float*)d_in[3];   // [H,H]

    // Output tuple flattened in order: fused [B,C,C,H] then att [B,C,C,S,S]
    float* fused = (float*)d_out;
    float* att   = (float*)d_out + (size_t)Bv * Cv * Cv * Hv;

    proj_kernel <<<dim3(2, 64, 1),  256>>>(inputs, W);
    att_kernel  <<<dim3(16, 16, Bv), 256>>>(inputs, mask, aself, att);
    fused_kernel<<<dim3(Cv, Bv, 1), 256>>>(inputs, fused);
}